// round 1
// baseline (speedup 1.0000x reference)
#include <cuda_runtime.h>

#define NN 50000
#define NE 600000
#define DD 128

// ---- static device scratch (no allocations allowed) ----
__device__ int   g_deg[NN + 1];
__device__ int   g_off[NN + 1];
__device__ int   g_cur[NN];
__device__ int   g_srcs[NE];
__device__ float g_bufA[NN * 256];   // also holds [N,256] MLP hidden
__device__ float g_bufB[NN * 128];

// ---------------- CSR build ----------------
__global__ void zero_kernel(int* __restrict__ deg, int* __restrict__ cur) {
    int i = blockIdx.x * blockDim.x + threadIdx.x;
    if (i <= NN) deg[i] = 0;
    if (i < NN)  cur[i] = 0;
}

__global__ void hist_kernel(const int* __restrict__ dst, int* __restrict__ deg) {
    int e = blockIdx.x * blockDim.x + threadIdx.x;
    if (e < NE) atomicAdd(&deg[dst[e]], 1);
}

// single-block Hillis-Steele scan over NN elements (exclusive prefix -> off)
__global__ void scan_kernel(const int* __restrict__ deg, int* __restrict__ off) {
    __shared__ int sm[1024];
    __shared__ int carry;
    if (threadIdx.x == 0) carry = 0;
    __syncthreads();
    for (int base = 0; base < NN; base += 1024) {
        int i = base + threadIdx.x;
        int v = (i < NN) ? deg[i] : 0;
        sm[threadIdx.x] = v;
        __syncthreads();
        for (int o = 1; o < 1024; o <<= 1) {
            int t = (threadIdx.x >= o) ? sm[threadIdx.x - o] : 0;
            __syncthreads();
            sm[threadIdx.x] += t;
            __syncthreads();
        }
        if (i < NN) off[i] = carry + sm[threadIdx.x] - v;
        __syncthreads();
        if (threadIdx.x == 0) carry += sm[1023];
        __syncthreads();
    }
    if (threadIdx.x == 0) off[NN] = carry;
}

__global__ void scatter_kernel(const int* __restrict__ src, const int* __restrict__ dst,
                               const int* __restrict__ off, int* __restrict__ cur,
                               int* __restrict__ srcs) {
    int e = blockIdx.x * blockDim.x + threadIdx.x;
    if (e < NE) {
        int d = dst[e];
        int p = off[d] + atomicAdd(&cur[d], 1);
        srcs[p] = src[e];
    }
}

// ---------------- GIN aggregate: out[n] = x[n] + sum_{e in N(n)} x[src(e)] ----------------
// warp per node, lane owns one float4 (32*4 = 128 floats)
__global__ void agg_kernel(const float4* __restrict__ x, const int* __restrict__ off,
                           const int* __restrict__ srcs, float4* __restrict__ out) {
    int gw   = (blockIdx.x * blockDim.x + threadIdx.x) >> 5;
    int lane = threadIdx.x & 31;
    if (gw >= NN) return;
    int s = off[gw], e = off[gw + 1];
    float4 acc = x[gw * 32 + lane];
    for (int i = s; i < e; i++) {
        int sc   = __ldg(&srcs[i]);          // warp-uniform broadcast
        float4 v = x[sc * 32 + lane];        // coalesced 512B row read
        acc.x += v.x; acc.y += v.y; acc.z += v.z; acc.w += v.w;
    }
    out[gw * 32 + lane] = acc;
}

// ---------------- GEMM + bias + relu:  out[nRows, nCols] = act(A[nRows,128] @ W[128,nCols] + b) ----------------
// BM=64, BN=128 per block (blockIdx.y tiles columns), 256 threads, thread-tile 8x4
__global__ void gemm_relu_kernel(const float* __restrict__ A, const float* __restrict__ W,
                                 const float* __restrict__ bias, float* __restrict__ out,
                                 int nRows, int nCols, int doRelu) {
    extern __shared__ float smem[];
    float* As = smem;              // 64 x 128
    float* Bs = smem + 64 * 128;   // 128 x 128

    const int tid     = threadIdx.x;
    const int rowBase = blockIdx.x * 64;
    const int colB4   = blockIdx.y * 32;   // column tile base in float4 units

    // load A tile (64x128) as float4, zero-fill past nRows
    {
        const float4* A4  = reinterpret_cast<const float4*>(A);
        float4*       As4 = reinterpret_cast<float4*>(As);
        #pragma unroll
        for (int t = 0; t < 8; t++) {
            int lin = tid + t * 256;           // 2048 float4 total
            int r   = lin >> 5;
            int c4  = lin & 31;
            int gr  = rowBase + r;
            float4 v = make_float4(0.f, 0.f, 0.f, 0.f);
            if (gr < nRows) v = A4[gr * 32 + c4];
            As4[lin] = v;
        }
    }
    // load B tile (128 x 128 cols)
    {
        const float4* W4  = reinterpret_cast<const float4*>(W);
        float4*       Bs4 = reinterpret_cast<float4*>(Bs);
        int stride4 = nCols >> 2;
        #pragma unroll
        for (int t = 0; t < 16; t++) {
            int lin = tid + t * 256;           // 4096 float4 total
            int r   = lin >> 5;
            int c4  = lin & 31;
            Bs4[lin] = W4[r * stride4 + colB4 + c4];
        }
    }
    __syncthreads();

    const int tx = tid & 31;   // col group (4 cols)
    const int ty = tid >> 5;   // row group (8 rows)
    float acc[8][4];
    #pragma unroll
    for (int r = 0; r < 8; r++) {
        acc[r][0] = acc[r][1] = acc[r][2] = acc[r][3] = 0.f;
    }

    const float4* Bs4 = reinterpret_cast<const float4*>(Bs);
    #pragma unroll 4
    for (int k = 0; k < 128; k++) {
        float4 bv = Bs4[k * 32 + tx];
        #pragma unroll
        for (int r = 0; r < 8; r++) {
            float av = As[(ty * 8 + r) * 128 + k];   // warp-uniform broadcast
            acc[r][0] += av * bv.x;
            acc[r][1] += av * bv.y;
            acc[r][2] += av * bv.z;
            acc[r][3] += av * bv.w;
        }
    }

    float4 bb = reinterpret_cast<const float4*>(bias)[colB4 + tx];
    int outStride4 = nCols >> 2;
    #pragma unroll
    for (int r = 0; r < 8; r++) {
        int gr = rowBase + ty * 8 + r;
        if (gr < nRows) {
            float4 v;
            v.x = acc[r][0] + bb.x;
            v.y = acc[r][1] + bb.y;
            v.z = acc[r][2] + bb.z;
            v.w = acc[r][3] + bb.w;
            if (doRelu) {
                v.x = fmaxf(v.x, 0.f); v.y = fmaxf(v.y, 0.f);
                v.z = fmaxf(v.z, 0.f); v.w = fmaxf(v.w, 0.f);
            }
            reinterpret_cast<float4*>(out)[gr * outStride4 + colB4 + tx] = v;
        }
    }
}

// ---------------- head: logits[N,10] = A[N,256] @ Wm2[256,10] + b ----------------
__global__ void head_kernel(const float* __restrict__ A, const float* __restrict__ W,
                            const float* __restrict__ b, float* __restrict__ out) {
    __shared__ float Ws[256 * 10];
    __shared__ float bs[10];
    for (int i = threadIdx.x; i < 2560; i += blockDim.x) Ws[i] = W[i];
    if (threadIdx.x < 10) bs[threadIdx.x] = b[threadIdx.x];
    __syncthreads();

    int gw   = (blockIdx.x * blockDim.x + threadIdx.x) >> 5;
    int lane = threadIdx.x & 31;
    if (gw >= NN) return;

    float acc[10];
    #pragma unroll
    for (int c = 0; c < 10; c++) acc[c] = 0.f;

    for (int k = lane; k < 256; k += 32) {
        float a = A[gw * 256 + k];
        #pragma unroll
        for (int c = 0; c < 10; c++) acc[c] += a * Ws[k * 10 + c];
    }
    #pragma unroll
    for (int c = 0; c < 10; c++) {
        #pragma unroll
        for (int o = 16; o; o >>= 1) acc[c] += __shfl_down_sync(0xffffffffu, acc[c], o);
    }
    if (lane == 0) {
        #pragma unroll
        for (int c = 0; c < 10; c++) out[gw * 10 + c] = acc[c] + bs[c];
    }
}

extern "C" void kernel_launch(void* const* d_in, const int* in_sizes, int n_in,
                              void* d_out, int out_size) {
    const float* x   = (const float*)d_in[0];
    const int*   ei  = (const int*)d_in[1];
    const float* W0  = (const float*)d_in[2];
    const float* b0  = (const float*)d_in[3];
    const float* W1  = (const float*)d_in[4];
    const float* b1  = (const float*)d_in[5];
    const float* W2  = (const float*)d_in[6];
    const float* b2  = (const float*)d_in[7];
    const float* Wm1 = (const float*)d_in[8];
    const float* bm1 = (const float*)d_in[9];
    const float* Wm2 = (const float*)d_in[10];
    const float* bm2 = (const float*)d_in[11];
    const int* src = ei;
    const int* dst = ei + NE;

    int *deg, *off, *cur, *srcs;
    float *bufA, *bufB;
    cudaGetSymbolAddress((void**)&deg,  g_deg);
    cudaGetSymbolAddress((void**)&off,  g_off);
    cudaGetSymbolAddress((void**)&cur,  g_cur);
    cudaGetSymbolAddress((void**)&srcs, g_srcs);
    cudaGetSymbolAddress((void**)&bufA, g_bufA);
    cudaGetSymbolAddress((void**)&bufB, g_bufB);

    cudaFuncSetAttribute(gemm_relu_kernel,
                         cudaFuncAttributeMaxDynamicSharedMemorySize, 96 * 1024);

    // ---- CSR build (once per launch; replayed by graph) ----
    zero_kernel<<<(NN + 1 + 255) / 256, 256>>>(deg, cur);
    hist_kernel<<<(NE + 255) / 256, 256>>>(dst, deg);
    scan_kernel<<<1, 1024>>>(deg, off);
    scatter_kernel<<<(NE + 255) / 256, 256>>>(src, dst, off, cur, srcs);

    dim3 g1((NN + 63) / 64, 1);
    dim3 g2((NN + 63) / 64, 2);
    int  warpBlocks = (NN * 32 + 255) / 256;
    const size_t smemB = 96 * 1024;

    // ---- layer 0 ----
    agg_kernel<<<warpBlocks, 256>>>((const float4*)x, off, srcs, (float4*)bufA);
    gemm_relu_kernel<<<g1, 256, smemB>>>(bufA, W0, b0, bufB, NN, 128, 1);
    // ---- layer 1 ----
    agg_kernel<<<warpBlocks, 256>>>((const float4*)bufB, off, srcs, (float4*)bufA);
    gemm_relu_kernel<<<g1, 256, smemB>>>(bufA, W1, b1, bufB, NN, 128, 1);
    // ---- layer 2 ----
    agg_kernel<<<warpBlocks, 256>>>((const float4*)bufB, off, srcs, (float4*)bufA);
    gemm_relu_kernel<<<g1, 256, smemB>>>(bufA, W2, b2, bufB, NN, 128, 1);
    // ---- MLP hidden [N,256] ----
    gemm_relu_kernel<<<g2, 256, smemB>>>(bufB, Wm1, bm1, bufA, NN, 256, 1);
    // ---- head [N,10] ----
    head_kernel<<<warpBlocks, 256>>>(bufA, Wm2, bm2, (float*)d_out);
}

// round 5
// speedup vs baseline: 1.3899x; 1.3899x over previous
#include <cuda_runtime.h>
#include <cuda_bf16.h>
#include <stdint.h>

#define NN 50000
#define NE 600000

// ---- static device scratch ----
__device__ int   g_deg[NN + 1];
__device__ int   g_off[NN + 1];
__device__ int   g_cur[NN];
__device__ int   g_srcs[NE];
__device__ float g_bufA[NN * 256];
__device__ float g_bufB[NN * 128];
// 5 prepped weight tiles (W0,W1,W2, Wm1[:,0:128], Wm1[:,128:256]) transposed to
// Wt[n][k] row-major bf16 (hi and lo split), 128x128 each
__device__ __nv_bfloat16 g_Bhi[5 * 16384];
__device__ __nv_bfloat16 g_Blo[5 * 16384];

// ===================== warp MMA helpers (base-target safe: sm_80+) =====================
__device__ __forceinline__ uint32_t smem_u32(const void* p) {
    uint32_t a;
    asm("{ .reg .u64 t; cvta.to.shared.u64 t, %1; cvt.u32.u64 %0, t; }" : "=r"(a) : "l"(p));
    return a;
}
__device__ __forceinline__ void ldsm_x4(uint32_t* a, uint32_t addr) {
    asm volatile("ldmatrix.sync.aligned.m8n8.x4.shared.b16 {%0,%1,%2,%3}, [%4];"
                 : "=r"(a[0]), "=r"(a[1]), "=r"(a[2]), "=r"(a[3]) : "r"(addr));
}
__device__ __forceinline__ void ldsm_x2(uint32_t* b, uint32_t addr) {
    asm volatile("ldmatrix.sync.aligned.m8n8.x2.shared.b16 {%0,%1}, [%2];"
                 : "=r"(b[0]), "=r"(b[1]) : "r"(addr));
}
__device__ __forceinline__ void mma_bf16(float* c, const uint32_t* a, const uint32_t* b) {
    asm volatile("mma.sync.aligned.m16n8k16.row.col.f32.bf16.bf16.f32 "
                 "{%0,%1,%2,%3}, {%4,%5,%6,%7}, {%8,%9}, {%0,%1,%2,%3};"
                 : "+f"(c[0]), "+f"(c[1]), "+f"(c[2]), "+f"(c[3])
                 : "r"(a[0]), "r"(a[1]), "r"(a[2]), "r"(a[3]), "r"(b[0]), "r"(b[1]));
}

// ===================== CSR build =====================
__global__ void zero_kernel(int* __restrict__ deg, int* __restrict__ cur) {
    int i = blockIdx.x * blockDim.x + threadIdx.x;
    if (i <= NN) deg[i] = 0;
    if (i < NN)  cur[i] = 0;
}
__global__ void hist_kernel(const int* __restrict__ dst, int* __restrict__ deg) {
    int e = blockIdx.x * blockDim.x + threadIdx.x;
    if (e < NE) atomicAdd(&deg[dst[e]], 1);
}
__global__ void scan_kernel(const int* __restrict__ deg, int* __restrict__ off) {
    __shared__ int sm[1024];
    __shared__ int carry;
    if (threadIdx.x == 0) carry = 0;
    __syncthreads();
    for (int base = 0; base < NN; base += 1024) {
        int i = base + threadIdx.x;
        int v = (i < NN) ? deg[i] : 0;
        sm[threadIdx.x] = v;
        __syncthreads();
        for (int o = 1; o < 1024; o <<= 1) {
            int t = (threadIdx.x >= o) ? sm[threadIdx.x - o] : 0;
            __syncthreads();
            sm[threadIdx.x] += t;
            __syncthreads();
        }
        if (i < NN) off[i] = carry + sm[threadIdx.x] - v;
        __syncthreads();
        if (threadIdx.x == 0) carry += sm[1023];
        __syncthreads();
    }
    if (threadIdx.x == 0) off[NN] = carry;
}
__global__ void scatter_kernel(const int* __restrict__ src, const int* __restrict__ dst,
                               const int* __restrict__ off, int* __restrict__ cur,
                               int* __restrict__ srcs) {
    int e = blockIdx.x * blockDim.x + threadIdx.x;
    if (e < NE) {
        int d = dst[e];
        int p = off[d] + atomicAdd(&cur[d], 1);
        srcs[p] = src[e];
    }
}

// ===================== GIN aggregate =====================
__global__ void agg_kernel(const float4* __restrict__ x, const int* __restrict__ off,
                           const int* __restrict__ srcs, float4* __restrict__ out) {
    int gw   = (blockIdx.x * blockDim.x + threadIdx.x) >> 5;
    int lane = threadIdx.x & 31;
    if (gw >= NN) return;
    int s = off[gw], e = off[gw + 1];
    float4 acc = x[gw * 32 + lane];
    for (int i = s; i < e; i++) {
        int sc   = __ldg(&srcs[i]);
        float4 v = x[sc * 32 + lane];
        acc.x += v.x; acc.y += v.y; acc.z += v.z; acc.w += v.w;
    }
    out[gw * 32 + lane] = acc;
}

// ===================== weight prep: transpose + bf16 hi/lo split =====================
// tile t: Wt[n][k] row-major; t=0..2 -> Wl[k*128+n]; t=3,4 -> Wm1[k*256 + (t-3)*128 + n]
__global__ void prep_w_kernel(const float* __restrict__ W0, const float* __restrict__ W1,
                              const float* __restrict__ W2, const float* __restrict__ Wm1,
                              __nv_bfloat16* __restrict__ bhi, __nv_bfloat16* __restrict__ blo) {
    int idx = blockIdx.x * blockDim.x + threadIdx.x;
    if (idx >= 5 * 16384) return;
    int t = idx >> 14;
    int e = idx & 16383;
    int n = e >> 7, k = e & 127;
    float w;
    if (t == 0)      w = W0[k * 128 + n];
    else if (t == 1) w = W1[k * 128 + n];
    else if (t == 2) w = W2[k * 128 + n];
    else             w = Wm1[k * 256 + (t - 3) * 128 + n];
    __nv_bfloat16 h = __float2bfloat16(w);
    __nv_bfloat16 l = __float2bfloat16(w - __bfloat162float(h));
    bhi[idx] = h;
    blo[idx] = l;
}

// ===================== tensor-core GEMM (mma.sync bf16 hi/lo split) =====================
// out[rows, colOff:colOff+128] = relu(A[rows,128] @ Wt^T + b)
// CTA: 128 rows x 128 cols, K=128 fully resident, 256 threads (8 warps, 2x4 warp grid,
// warp tile 64x32 = 4x4 m16n8k16 tiles). Smem rows padded to 136 bf16 (272B).
#define LDA    136                 // padded bf16 stride
#define A_HI   0
#define A_LO   34816
#define B_HI   69632
#define B_LO   104448
#define SM_BS  139264
#define SM_BYTES (139264 + 512)

__global__ void __launch_bounds__(256, 1)
gemm_tc_kernel(const float* __restrict__ A,
               const __nv_bfloat16* __restrict__ gBhi,
               const __nv_bfloat16* __restrict__ gBlo,
               const float* __restrict__ bias,
               float* __restrict__ out,
               int tile0, int outCols) {
    extern __shared__ char smem[];
    const int tid  = threadIdx.x;
    const int wid  = tid >> 5;
    const int lane = tid & 31;
    const int t = tile0 + blockIdx.y;
    const int colOff = blockIdx.y * 128;
    const int rowBase = blockIdx.x * 128;

    // ---- load A tile (fp32 -> bf16 hi/lo, padded smem) ----
    {
        const float4* A4 = reinterpret_cast<const float4*>(A);
        #pragma unroll
        for (int i = 0; i < 16; i++) {
            int lin = tid + i * 256;          // 4096 float4
            int r   = lin >> 5;
            int c4  = lin & 31;
            int gr  = rowBase + r;
            float4 f = (gr < NN) ? A4[gr * 32 + c4] : make_float4(0.f, 0.f, 0.f, 0.f);
            __nv_bfloat162 h0 = __floats2bfloat162_rn(f.x, f.y);
            __nv_bfloat162 h1 = __floats2bfloat162_rn(f.z, f.w);
            float2 hf0 = __bfloat1622float2(h0);
            float2 hf1 = __bfloat1622float2(h1);
            __nv_bfloat162 l0 = __floats2bfloat162_rn(f.x - hf0.x, f.y - hf0.y);
            __nv_bfloat162 l1 = __floats2bfloat162_rn(f.z - hf1.x, f.w - hf1.y);
            uint2 hv = make_uint2(reinterpret_cast<uint32_t&>(h0), reinterpret_cast<uint32_t&>(h1));
            uint2 lv = make_uint2(reinterpret_cast<uint32_t&>(l0), reinterpret_cast<uint32_t&>(l1));
            int boff = r * (LDA * 2) + c4 * 8;
            *reinterpret_cast<uint2*>(smem + A_HI + boff) = hv;
            *reinterpret_cast<uint2*>(smem + A_LO + boff) = lv;
        }
    }
    // ---- load B tiles (prepped bf16, linear copy into padded smem) ----
    {
        const uint4* shi = reinterpret_cast<const uint4*>(gBhi + t * 16384);
        const uint4* slo = reinterpret_cast<const uint4*>(gBlo + t * 16384);
        #pragma unroll
        for (int i = 0; i < 8; i++) {
            int lin = tid + i * 256;          // 2048 uint4
            int n = lin >> 4, q = lin & 15;
            int boff = n * (LDA * 2) + q * 16;
            *reinterpret_cast<uint4*>(smem + B_HI + boff) = shi[lin];
            *reinterpret_cast<uint4*>(smem + B_LO + boff) = slo[lin];
        }
        if (tid < 128) reinterpret_cast<float*>(smem + SM_BS)[tid] = bias[colOff + tid];
    }
    __syncthreads();

    // ---- warp MMA mainloop ----
    const int wm = (wid & 1) * 64;
    const int wn = (wid >> 1) * 32;
    float acc[4][4][4];
    #pragma unroll
    for (int mt = 0; mt < 4; mt++)
        #pragma unroll
        for (int nt = 0; nt < 4; nt++)
            #pragma unroll
            for (int j = 0; j < 4; j++) acc[mt][nt][j] = 0.f;

    const uint32_t sb = smem_u32(smem);
    const uint32_t aBaseHi = sb + A_HI + (wm + (lane & 15)) * (LDA * 2) + (lane >> 4) * 16;
    const uint32_t aBaseLo = aBaseHi + (A_LO - A_HI);
    const uint32_t bBaseHi = sb + B_HI + (wn + (lane & 7)) * (LDA * 2) + ((lane >> 3) & 1) * 16;
    const uint32_t bBaseLo = bBaseHi + (B_LO - B_HI);

    #pragma unroll
    for (int ks = 0; ks < 8; ks++) {
        uint32_t bh[4][2], bl[4][2];
        #pragma unroll
        for (int nt = 0; nt < 4; nt++) {
            ldsm_x2(bh[nt], bBaseHi + nt * 8 * (LDA * 2) + ks * 32);
            ldsm_x2(bl[nt], bBaseLo + nt * 8 * (LDA * 2) + ks * 32);
        }
        #pragma unroll
        for (int mt = 0; mt < 4; mt++) {
            uint32_t ah[4], al[4];
            ldsm_x4(ah, aBaseHi + mt * 16 * (LDA * 2) + ks * 32);
            ldsm_x4(al, aBaseLo + mt * 16 * (LDA * 2) + ks * 32);
            #pragma unroll
            for (int nt = 0; nt < 4; nt++) {
                mma_bf16(acc[mt][nt], ah, bh[nt]);
                mma_bf16(acc[mt][nt], ah, bl[nt]);
                mma_bf16(acc[mt][nt], al, bh[nt]);
            }
        }
    }

    // ---- epilogue: bias + relu, fp32 store ----
    const float* bs = reinterpret_cast<const float*>(smem + SM_BS);
    #pragma unroll
    for (int mt = 0; mt < 4; mt++) {
        #pragma unroll
        for (int nt = 0; nt < 4; nt++) {
            int lc = wn + nt * 8 + (lane & 3) * 2;
            int r0 = rowBase + wm + mt * 16 + (lane >> 2);
            float b0 = bs[lc], b1 = bs[lc + 1];
            int c = colOff + lc;
            if (r0 < NN) {
                float2 v;
                v.x = fmaxf(acc[mt][nt][0] + b0, 0.f);
                v.y = fmaxf(acc[mt][nt][1] + b1, 0.f);
                *reinterpret_cast<float2*>(out + (size_t)r0 * outCols + c) = v;
            }
            if (r0 + 8 < NN) {
                float2 v;
                v.x = fmaxf(acc[mt][nt][2] + b0, 0.f);
                v.y = fmaxf(acc[mt][nt][3] + b1, 0.f);
                *reinterpret_cast<float2*>(out + (size_t)(r0 + 8) * outCols + c) = v;
            }
        }
    }
}

// ===================== head =====================
__global__ void head_kernel(const float* __restrict__ A, const float* __restrict__ W,
                            const float* __restrict__ b, float* __restrict__ out) {
    __shared__ float Ws[256 * 10];
    __shared__ float bs[10];
    for (int i = threadIdx.x; i < 2560; i += blockDim.x) Ws[i] = W[i];
    if (threadIdx.x < 10) bs[threadIdx.x] = b[threadIdx.x];
    __syncthreads();

    int gw   = (blockIdx.x * blockDim.x + threadIdx.x) >> 5;
    int lane = threadIdx.x & 31;
    if (gw >= NN) return;

    float acc[10];
    #pragma unroll
    for (int c = 0; c < 10; c++) acc[c] = 0.f;
    for (int k = lane; k < 256; k += 32) {
        float a = A[gw * 256 + k];
        #pragma unroll
        for (int c = 0; c < 10; c++) acc[c] += a * Ws[k * 10 + c];
    }
    #pragma unroll
    for (int c = 0; c < 10; c++) {
        #pragma unroll
        for (int o = 16; o; o >>= 1) acc[c] += __shfl_down_sync(0xffffffffu, acc[c], o);
    }
    if (lane == 0) {
        #pragma unroll
        for (int c = 0; c < 10; c++) out[gw * 10 + c] = acc[c] + bs[c];
    }
}

// ===================== host =====================
extern "C" void kernel_launch(void* const* d_in, const int* in_sizes, int n_in,
                              void* d_out, int out_size) {
    const float* x   = (const float*)d_in[0];
    const int*   ei  = (const int*)d_in[1];
    const float* W0  = (const float*)d_in[2];
    const float* b0  = (const float*)d_in[3];
    const float* W1  = (const float*)d_in[4];
    const float* b1  = (const float*)d_in[5];
    const float* W2  = (const float*)d_in[6];
    const float* b2  = (const float*)d_in[7];
    const float* Wm1 = (const float*)d_in[8];
    const float* bm1 = (const float*)d_in[9];
    const float* Wm2 = (const float*)d_in[10];
    const float* bm2 = (const float*)d_in[11];
    const int* src = ei;
    const int* dst = ei + NE;

    int *deg, *off, *cur, *srcs;
    float *bufA, *bufB;
    __nv_bfloat16 *bhi, *blo;
    cudaGetSymbolAddress((void**)&deg,  g_deg);
    cudaGetSymbolAddress((void**)&off,  g_off);
    cudaGetSymbolAddress((void**)&cur,  g_cur);
    cudaGetSymbolAddress((void**)&srcs, g_srcs);
    cudaGetSymbolAddress((void**)&bufA, g_bufA);
    cudaGetSymbolAddress((void**)&bufB, g_bufB);
    cudaGetSymbolAddress((void**)&bhi,  g_Bhi);
    cudaGetSymbolAddress((void**)&blo,  g_Blo);

    cudaFuncSetAttribute(gemm_tc_kernel,
                         cudaFuncAttributeMaxDynamicSharedMemorySize, SM_BYTES);

    // weight prep + CSR build
    prep_w_kernel<<<(5 * 16384 + 255) / 256, 256>>>(W0, W1, W2, Wm1, bhi, blo);
    zero_kernel<<<(NN + 1 + 255) / 256, 256>>>(deg, cur);
    hist_kernel<<<(NE + 255) / 256, 256>>>(dst, deg);
    scan_kernel<<<1, 1024>>>(deg, off);
    scatter_kernel<<<(NE + 255) / 256, 256>>>(src, dst, off, cur, srcs);

    const int warpBlocks = (NN * 32 + 255) / 256;
    const int gemmBlocks = (NN + 127) / 128;   // 391

    // layer 0
    agg_kernel<<<warpBlocks, 256>>>((const float4*)x, off, srcs, (float4*)bufA);
    gemm_tc_kernel<<<dim3(gemmBlocks, 1), 256, SM_BYTES>>>(bufA, bhi, blo, b0, bufB, 0, 128);
    // layer 1
    agg_kernel<<<warpBlocks, 256>>>((const float4*)bufB, off, srcs, (float4*)bufA);
    gemm_tc_kernel<<<dim3(gemmBlocks, 1), 256, SM_BYTES>>>(bufA, bhi, blo, b1, bufB, 1, 128);
    // layer 2
    agg_kernel<<<warpBlocks, 256>>>((const float4*)bufB, off, srcs, (float4*)bufA);
    gemm_tc_kernel<<<dim3(gemmBlocks, 1), 256, SM_BYTES>>>(bufA, bhi, blo, b2, bufB, 2, 128);
    // MLP hidden [N,256] as two 128-col tiles
    gemm_tc_kernel<<<dim3(gemmBlocks, 2), 256, SM_BYTES>>>(bufB, bhi, blo, bm1, bufA, 3, 256);
    // head
    head_kernel<<<warpBlocks, 256>>>(bufA, Wm2, bm2, (float*)d_out);
}

// round 7
// speedup vs baseline: 1.7137x; 1.2330x over previous
#include <cuda_runtime.h>
#include <cuda_bf16.h>
#include <stdint.h>

#define NN 50000
#define NE 600000
#define SCAN_BLOCKS ((NN + 1 + 1023) / 1024)   // 49

// ---- static device scratch ----
__device__ int   g_deg[NN + 1];
__device__ int   g_off[NN + 1];
__device__ int   g_cur[NN];
__device__ int   g_srcs[NE];
__device__ int   g_bsums[64];
__device__ float g_bufA[NN * 256];
__device__ float g_bufB[NN * 128];
// 5 prepped weight tiles (W0,W1,W2, Wm1[:,0:128], Wm1[:,128:256]) transposed to
// Wt[n][k] row-major bf16 (hi and lo split), 128x128 each
__device__ __nv_bfloat16 g_Bhi[5 * 16384];
__device__ __nv_bfloat16 g_Blo[5 * 16384];

// ===================== warp MMA helpers (base-target safe: sm_80+) =====================
__device__ __forceinline__ uint32_t smem_u32(const void* p) {
    uint32_t a;
    asm("{ .reg .u64 t; cvta.to.shared.u64 t, %1; cvt.u32.u64 %0, t; }" : "=r"(a) : "l"(p));
    return a;
}
__device__ __forceinline__ void ldsm_x4(uint32_t* a, uint32_t addr) {
    asm volatile("ldmatrix.sync.aligned.m8n8.x4.shared.b16 {%0,%1,%2,%3}, [%4];"
                 : "=r"(a[0]), "=r"(a[1]), "=r"(a[2]), "=r"(a[3]) : "r"(addr));
}
__device__ __forceinline__ void ldsm_x2(uint32_t* b, uint32_t addr) {
    asm volatile("ldmatrix.sync.aligned.m8n8.x2.shared.b16 {%0,%1}, [%2];"
                 : "=r"(b[0]), "=r"(b[1]) : "r"(addr));
}
__device__ __forceinline__ void mma_bf16(float* c, const uint32_t* a, const uint32_t* b) {
    asm volatile("mma.sync.aligned.m16n8k16.row.col.f32.bf16.bf16.f32 "
                 "{%0,%1,%2,%3}, {%4,%5,%6,%7}, {%8,%9}, {%0,%1,%2,%3};"
                 : "+f"(c[0]), "+f"(c[1]), "+f"(c[2]), "+f"(c[3])
                 : "r"(a[0]), "r"(a[1]), "r"(a[2]), "r"(a[3]), "r"(b[0]), "r"(b[1]));
}

// ===================== CSR build =====================
__global__ void zero_kernel(int* __restrict__ deg, int* __restrict__ cur) {
    int i = blockIdx.x * blockDim.x + threadIdx.x;
    if (i <= NN) deg[i] = 0;
    if (i < NN)  cur[i] = 0;
}
__global__ void hist_kernel(const int* __restrict__ dst, int* __restrict__ deg) {
    int e = blockIdx.x * blockDim.x + threadIdx.x;
    if (e < NE) atomicAdd(&deg[dst[e]], 1);
}

// ---- multi-block exclusive scan over NN+1 elements (element NN is virtual 0) ----
__global__ void blockscan_kernel(const int* __restrict__ deg, int* __restrict__ off,
                                 int* __restrict__ bsums) {
    __shared__ int wsum[32];
    int i = blockIdx.x * 1024 + threadIdx.x;
    int v = (i < NN) ? deg[i] : 0;
    int lane = threadIdx.x & 31, w = threadIdx.x >> 5;
    int inc = v;
    #pragma unroll
    for (int o = 1; o < 32; o <<= 1) {
        int t = __shfl_up_sync(0xffffffffu, inc, o);
        if (lane >= o) inc += t;
    }
    if (lane == 31) wsum[w] = inc;
    __syncthreads();
    if (w == 0) {
        int s = wsum[lane];
        #pragma unroll
        for (int o = 1; o < 32; o <<= 1) {
            int t = __shfl_up_sync(0xffffffffu, s, o);
            if (lane >= o) s += t;
        }
        wsum[lane] = s;
    }
    __syncthreads();
    int prefix = (w > 0) ? wsum[w - 1] : 0;
    if (i <= NN) off[i] = prefix + inc - v;           // local exclusive
    if (threadIdx.x == 1023) bsums[blockIdx.x] = wsum[31];
}
__global__ void scanb_kernel(int* __restrict__ bsums) {   // exclusive scan of SCAN_BLOCKS values
    __shared__ int sm[64];
    int lane = threadIdx.x;
    int v = (lane < SCAN_BLOCKS) ? bsums[lane] : 0;
    sm[lane] = v;
    __syncthreads();
    for (int o = 1; o < 64; o <<= 1) {
        int t = (lane >= o) ? sm[lane - o] : 0;
        __syncthreads();
        sm[lane] += t;
        __syncthreads();
    }
    if (lane < SCAN_BLOCKS) bsums[lane] = sm[lane] - v;
}
__global__ void addoff_kernel(int* __restrict__ off, const int* __restrict__ bsums) {
    int i = blockIdx.x * 1024 + threadIdx.x;
    if (i <= NN) off[i] += bsums[blockIdx.x];
}

__global__ void scatter_kernel(const int* __restrict__ src, const int* __restrict__ dst,
                               const int* __restrict__ off, int* __restrict__ cur,
                               int* __restrict__ srcs) {
    int e = blockIdx.x * blockDim.x + threadIdx.x;
    if (e < NE) {
        int d = dst[e];
        int p = off[d] + atomicAdd(&cur[d], 1);
        srcs[p] = src[e];
    }
}

// ===================== GIN aggregate =====================
__global__ void agg_kernel(const float4* __restrict__ x, const int* __restrict__ off,
                           const int* __restrict__ srcs, float4* __restrict__ out) {
    int gw   = (blockIdx.x * blockDim.x + threadIdx.x) >> 5;
    int lane = threadIdx.x & 31;
    if (gw >= NN) return;
    int s = off[gw], e = off[gw + 1];
    float4 acc = x[gw * 32 + lane];
    #pragma unroll 2
    for (int i = s; i < e; i++) {
        int sc   = __ldg(&srcs[i]);
        float4 v = x[sc * 32 + lane];
        acc.x += v.x; acc.y += v.y; acc.z += v.z; acc.w += v.w;
    }
    out[gw * 32 + lane] = acc;
}

// ===================== weight prep: transpose + bf16 hi/lo split =====================
__global__ void prep_w_kernel(const float* __restrict__ W0, const float* __restrict__ W1,
                              const float* __restrict__ W2, const float* __restrict__ Wm1,
                              __nv_bfloat16* __restrict__ bhi, __nv_bfloat16* __restrict__ blo) {
    int idx = blockIdx.x * blockDim.x + threadIdx.x;
    if (idx >= 5 * 16384) return;
    int t = idx >> 14;
    int e = idx & 16383;
    int n = e >> 7, k = e & 127;
    float w;
    if (t == 0)      w = W0[k * 128 + n];
    else if (t == 1) w = W1[k * 128 + n];
    else if (t == 2) w = W2[k * 128 + n];
    else             w = Wm1[k * 256 + (t - 3) * 128 + n];
    __nv_bfloat16 h = __float2bfloat16(w);
    __nv_bfloat16 l = __float2bfloat16(w - __bfloat162float(h));
    bhi[idx] = h;
    blo[idx] = l;
}

// ===================== tensor-core GEMM (mma.sync bf16 hi/lo split) =====================
#define LDA    136                 // padded bf16 stride
#define A_HI   0
#define A_LO   34816
#define B_HI   69632
#define B_LO   104448
#define SM_BS  139264
#define SM_BYTES (139264 + 512)

__global__ void __launch_bounds__(256, 1)
gemm_tc_kernel(const float* __restrict__ A,
               const __nv_bfloat16* __restrict__ gBhi,
               const __nv_bfloat16* __restrict__ gBlo,
               const float* __restrict__ bias,
               float* __restrict__ out,
               int tile0, int outCols) {
    extern __shared__ char smem[];
    const int tid  = threadIdx.x;
    const int wid  = tid >> 5;
    const int lane = tid & 31;
    const int t = tile0 + blockIdx.y;
    const int colOff = blockIdx.y * 128;
    const int rowBase = blockIdx.x * 128;

    // ---- load A tile (fp32 -> bf16 hi/lo, padded smem) ----
    {
        const float4* A4 = reinterpret_cast<const float4*>(A);
        #pragma unroll
        for (int i = 0; i < 16; i++) {
            int lin = tid + i * 256;          // 4096 float4
            int r   = lin >> 5;
            int c4  = lin & 31;
            int gr  = rowBase + r;
            float4 f = (gr < NN) ? A4[gr * 32 + c4] : make_float4(0.f, 0.f, 0.f, 0.f);
            __nv_bfloat162 h0 = __floats2bfloat162_rn(f.x, f.y);
            __nv_bfloat162 h1 = __floats2bfloat162_rn(f.z, f.w);
            float2 hf0 = __bfloat1622float2(h0);
            float2 hf1 = __bfloat1622float2(h1);
            __nv_bfloat162 l0 = __floats2bfloat162_rn(f.x - hf0.x, f.y - hf0.y);
            __nv_bfloat162 l1 = __floats2bfloat162_rn(f.z - hf1.x, f.w - hf1.y);
            uint2 hv = make_uint2(reinterpret_cast<uint32_t&>(h0), reinterpret_cast<uint32_t&>(h1));
            uint2 lv = make_uint2(reinterpret_cast<uint32_t&>(l0), reinterpret_cast<uint32_t&>(l1));
            int boff = r * (LDA * 2) + c4 * 8;
            *reinterpret_cast<uint2*>(smem + A_HI + boff) = hv;
            *reinterpret_cast<uint2*>(smem + A_LO + boff) = lv;
        }
    }
    // ---- load B tiles (prepped bf16, linear copy into padded smem) ----
    {
        const uint4* shi = reinterpret_cast<const uint4*>(gBhi + t * 16384);
        const uint4* slo = reinterpret_cast<const uint4*>(gBlo + t * 16384);
        #pragma unroll
        for (int i = 0; i < 8; i++) {
            int lin = tid + i * 256;          // 2048 uint4
            int n = lin >> 4, q = lin & 15;
            int boff = n * (LDA * 2) + q * 16;
            *reinterpret_cast<uint4*>(smem + B_HI + boff) = shi[lin];
            *reinterpret_cast<uint4*>(smem + B_LO + boff) = slo[lin];
        }
        if (tid < 128) reinterpret_cast<float*>(smem + SM_BS)[tid] = bias[colOff + tid];
    }
    __syncthreads();

    // ---- warp MMA mainloop ----
    const int wm = (wid & 1) * 64;
    const int wn = (wid >> 1) * 32;
    float acc[4][4][4];
    #pragma unroll
    for (int mt = 0; mt < 4; mt++)
        #pragma unroll
        for (int nt = 0; nt < 4; nt++)
            #pragma unroll
            for (int j = 0; j < 4; j++) acc[mt][nt][j] = 0.f;

    const uint32_t sb = smem_u32(smem);
    const uint32_t aBaseHi = sb + A_HI + (wm + (lane & 15)) * (LDA * 2) + (lane >> 4) * 16;
    const uint32_t aBaseLo = aBaseHi + (A_LO - A_HI);
    const uint32_t bBaseHi = sb + B_HI + (wn + (lane & 7)) * (LDA * 2) + ((lane >> 3) & 1) * 16;
    const uint32_t bBaseLo = bBaseHi + (B_LO - B_HI);

    #pragma unroll
    for (int ks = 0; ks < 8; ks++) {
        uint32_t bh[4][2], bl[4][2];
        #pragma unroll
        for (int nt = 0; nt < 4; nt++) {
            ldsm_x2(bh[nt], bBaseHi + nt * 8 * (LDA * 2) + ks * 32);
            ldsm_x2(bl[nt], bBaseLo + nt * 8 * (LDA * 2) + ks * 32);
        }
        #pragma unroll
        for (int mt = 0; mt < 4; mt++) {
            uint32_t ah[4], al[4];
            ldsm_x4(ah, aBaseHi + mt * 16 * (LDA * 2) + ks * 32);
            ldsm_x4(al, aBaseLo + mt * 16 * (LDA * 2) + ks * 32);
            #pragma unroll
            for (int nt = 0; nt < 4; nt++) {
                mma_bf16(acc[mt][nt], ah, bh[nt]);
                mma_bf16(acc[mt][nt], ah, bl[nt]);
                mma_bf16(acc[mt][nt], al, bh[nt]);
            }
        }
    }

    // ---- epilogue: bias + relu, fp32 store ----
    const float* bs = reinterpret_cast<const float*>(smem + SM_BS);
    #pragma unroll
    for (int mt = 0; mt < 4; mt++) {
        #pragma unroll
        for (int nt = 0; nt < 4; nt++) {
            int lc = wn + nt * 8 + (lane & 3) * 2;
            int r0 = rowBase + wm + mt * 16 + (lane >> 2);
            float b0 = bs[lc], b1 = bs[lc + 1];
            int c = colOff + lc;
            if (r0 < NN) {
                float2 v;
                v.x = fmaxf(acc[mt][nt][0] + b0, 0.f);
                v.y = fmaxf(acc[mt][nt][1] + b1, 0.f);
                *reinterpret_cast<float2*>(out + (size_t)r0 * outCols + c) = v;
            }
            if (r0 + 8 < NN) {
                float2 v;
                v.x = fmaxf(acc[mt][nt][2] + b0, 0.f);
                v.y = fmaxf(acc[mt][nt][3] + b1, 0.f);
                *reinterpret_cast<float2*>(out + (size_t)(r0 + 8) * outCols + c) = v;
            }
        }
    }
}

// ===================== head =====================
__global__ void head_kernel(const float* __restrict__ A, const float* __restrict__ W,
                            const float* __restrict__ b, float* __restrict__ out) {
    __shared__ float Ws[256 * 10];
    __shared__ float bs[10];
    for (int i = threadIdx.x; i < 2560; i += blockDim.x) Ws[i] = W[i];
    if (threadIdx.x < 10) bs[threadIdx.x] = b[threadIdx.x];
    __syncthreads();

    int gw   = (blockIdx.x * blockDim.x + threadIdx.x) >> 5;
    int lane = threadIdx.x & 31;
    if (gw >= NN) return;

    float acc[10];
    #pragma unroll
    for (int c = 0; c < 10; c++) acc[c] = 0.f;
    for (int k = lane; k < 256; k += 32) {
        float a = A[gw * 256 + k];
        #pragma unroll
        for (int c = 0; c < 10; c++) acc[c] += a * Ws[k * 10 + c];
    }
    #pragma unroll
    for (int c = 0; c < 10; c++) {
        #pragma unroll
        for (int o = 16; o; o >>= 1) acc[c] += __shfl_down_sync(0xffffffffu, acc[c], o);
    }
    if (lane == 0) {
        #pragma unroll
        for (int c = 0; c < 10; c++) out[gw * 10 + c] = acc[c] + bs[c];
    }
}

// ===================== host =====================
extern "C" void kernel_launch(void* const* d_in, const int* in_sizes, int n_in,
                              void* d_out, int out_size) {
    const float* x   = (const float*)d_in[0];
    const int*   ei  = (const int*)d_in[1];
    const float* W0  = (const float*)d_in[2];
    const float* b0  = (const float*)d_in[3];
    const float* W1  = (const float*)d_in[4];
    const float* b1  = (const float*)d_in[5];
    const float* W2  = (const float*)d_in[6];
    const float* b2  = (const float*)d_in[7];
    const float* Wm1 = (const float*)d_in[8];
    const float* bm1 = (const float*)d_in[9];
    const float* Wm2 = (const float*)d_in[10];
    const float* bm2 = (const float*)d_in[11];
    const int* src = ei;
    const int* dst = ei + NE;

    int *deg, *off, *cur, *srcs, *bsums;
    float *bufA, *bufB;
    __nv_bfloat16 *bhi, *blo;
    cudaGetSymbolAddress((void**)&deg,   g_deg);
    cudaGetSymbolAddress((void**)&off,   g_off);
    cudaGetSymbolAddress((void**)&cur,   g_cur);
    cudaGetSymbolAddress((void**)&srcs,  g_srcs);
    cudaGetSymbolAddress((void**)&bsums, g_bsums);
    cudaGetSymbolAddress((void**)&bufA,  g_bufA);
    cudaGetSymbolAddress((void**)&bufB,  g_bufB);
    cudaGetSymbolAddress((void**)&bhi,   g_Bhi);
    cudaGetSymbolAddress((void**)&blo,   g_Blo);

    cudaFuncSetAttribute(gemm_tc_kernel,
                         cudaFuncAttributeMaxDynamicSharedMemorySize, SM_BYTES);

    // weight prep + CSR build
    prep_w_kernel<<<(5 * 16384 + 255) / 256, 256>>>(W0, W1, W2, Wm1, bhi, blo);
    zero_kernel<<<(NN + 1 + 255) / 256, 256>>>(deg, cur);
    hist_kernel<<<(NE + 255) / 256, 256>>>(dst, deg);
    blockscan_kernel<<<SCAN_BLOCKS, 1024>>>(deg, off, bsums);
    scanb_kernel<<<1, 64>>>(bsums);
    addoff_kernel<<<SCAN_BLOCKS, 1024>>>(off, bsums);
    scatter_kernel<<<(NE + 255) / 256, 256>>>(src, dst, off, cur, srcs);

    const int warpBlocks = (NN * 32 + 255) / 256;
    const int gemmBlocks = (NN + 127) / 128;   // 391

    // layer 0
    agg_kernel<<<warpBlocks, 256>>>((const float4*)x, off, srcs, (float4*)bufA);
    gemm_tc_kernel<<<dim3(gemmBlocks, 1), 256, SM_BYTES>>>(bufA, bhi, blo, b0, bufB, 0, 128);
    // layer 1
    agg_kernel<<<warpBlocks, 256>>>((const float4*)bufB, off, srcs, (float4*)bufA);
    gemm_tc_kernel<<<dim3(gemmBlocks, 1), 256, SM_BYTES>>>(bufA, bhi, blo, b1, bufB, 1, 128);
    // layer 2
    agg_kernel<<<warpBlocks, 256>>>((const float4*)bufB, off, srcs, (float4*)bufA);
    gemm_tc_kernel<<<dim3(gemmBlocks, 1), 256, SM_BYTES>>>(bufA, bhi, blo, b2, bufB, 2, 128);
    // MLP hidden [N,256] as two 128-col tiles
    gemm_tc_kernel<<<dim3(gemmBlocks, 2), 256, SM_BYTES>>>(bufB, bhi, blo, bm1, bufA, 3, 256);
    // head
    head_kernel<<<warpBlocks, 256>>>(bufA, Wm2, bm2, (float*)d_out);
}